// round 1
// baseline (speedup 1.0000x reference)
#include <cuda_runtime.h>
#include <math.h>

#define BB   256
#define NT   196
#define DIM  384
#define HH   12
#define KD   32
#define VD   32
#define MM   (BB*NT)          // 50176
#define FF   (HH*(2*KD+VD))   // 1152
#define QK_SCALE 0.17677669529663687f  // 32^-0.5

// ---------------- scratch (static device allocations; no cudaMalloc) ----------
__device__ float g_xn [MM*DIM];          // layernorm output        77 MB
__device__ float g_q  [BB*HH*NT*KD];     // [b][h][n][kd]           19 MB
__device__ float g_k  [BB*HH*NT*KD];
__device__ float g_v  [BB*HH*NT*VD];
__device__ float g_att[MM*DIM];          // attention out [m][h*32+vd]

// ---------------- kernel 1: LayerNorm, one warp per row -----------------------
__global__ void __launch_bounds__(256) ln_kernel(const float* __restrict__ x,
                                                 const float* __restrict__ w,
                                                 const float* __restrict__ b) {
    int row  = blockIdx.x * 8 + (threadIdx.x >> 5);
    int lane = threadIdx.x & 31;
    const float* xr = x + (size_t)row * DIM;
    float4 v[3];
    float sum = 0.f, sq = 0.f;
#pragma unroll
    for (int j = 0; j < 3; j++) {
        v[j] = *(const float4*)(xr + j*128 + lane*4);
        sum += v[j].x + v[j].y + v[j].z + v[j].w;
        sq  += v[j].x*v[j].x + v[j].y*v[j].y + v[j].z*v[j].z + v[j].w*v[j].w;
    }
#pragma unroll
    for (int o = 16; o; o >>= 1) {
        sum += __shfl_xor_sync(0xffffffffu, sum, o);
        sq  += __shfl_xor_sync(0xffffffffu, sq,  o);
    }
    float mean = sum * (1.f/DIM);
    float var  = sq  * (1.f/DIM) - mean*mean;
    float inv  = rsqrtf(var + 1e-5f);
    float* orow = g_xn + (size_t)row * DIM;
#pragma unroll
    for (int j = 0; j < 3; j++) {
        float4 ww = *(const float4*)(w + j*128 + lane*4);
        float4 bb = *(const float4*)(b + j*128 + lane*4);
        float4 o4;
        o4.x = (v[j].x - mean)*inv*ww.x + bb.x;
        o4.y = (v[j].y - mean)*inv*ww.y + bb.y;
        o4.z = (v[j].z - mean)*inv*ww.z + bb.z;
        o4.w = (v[j].w - mean)*inv*ww.w + bb.w;
        *(float4*)(orow + j*128 + lane*4) = o4;
    }
}

// ---------------- kernel 2/4: SGEMM 128x64x16, 8x4 per thread ------------------
// C[m][nn] = sum_k A[m][k] * W[nn][k] + bias[nn]
// QKV=true : A = g_xn, scatter epilogue into g_q/g_k/g_v
// QKV=false: A = g_att, dense epilogue into C (d_out)
template<bool QKV>
__global__ void __launch_bounds__(256) gemm_kernel(const float* __restrict__ W,
                                                   const float* __restrict__ bias,
                                                   float* __restrict__ C) {
    __shared__ float As[16][128];
    __shared__ float Bs[16][64];
    const float* A = QKV ? g_xn : g_att;

    int tid  = threadIdx.x;
    int tx   = tid & 15;          // 0..15 -> col block of 4
    int ty   = tid >> 4;          // 0..15 -> row block of 8
    int row0 = blockIdx.x * 128;
    int col0 = blockIdx.y * 64;

    int lm = tid >> 2;            // 0..63
    int kq = (tid & 3) * 4;       // 0,4,8,12
    const float* Aptr  = A + (size_t)(row0 + lm)      * DIM + kq;
    const float* Aptr2 = A + (size_t)(row0 + lm + 64) * DIM + kq;
    const float* Wptr  = W + (size_t)(col0 + lm)      * DIM + kq;

    float acc[8][4] = {};

    for (int kt = 0; kt < DIM; kt += 16) {
        float4 a0 = *(const float4*)(Aptr  + kt);
        float4 a1 = *(const float4*)(Aptr2 + kt);
        float4 w0 = *(const float4*)(Wptr  + kt);
        __syncthreads();
        As[kq+0][lm]    = a0.x; As[kq+1][lm]    = a0.y; As[kq+2][lm]    = a0.z; As[kq+3][lm]    = a0.w;
        As[kq+0][lm+64] = a1.x; As[kq+1][lm+64] = a1.y; As[kq+2][lm+64] = a1.z; As[kq+3][lm+64] = a1.w;
        Bs[kq+0][lm]    = w0.x; Bs[kq+1][lm]    = w0.y; Bs[kq+2][lm]    = w0.z; Bs[kq+3][lm]    = w0.w;
        __syncthreads();
#pragma unroll
        for (int k = 0; k < 16; k++) {
            float4 ra0 = *(const float4*)&As[k][ty*8];
            float4 ra1 = *(const float4*)&As[k][ty*8+4];
            float4 rb  = *(const float4*)&Bs[k][tx*4];
            float av[8] = {ra0.x, ra0.y, ra0.z, ra0.w, ra1.x, ra1.y, ra1.z, ra1.w};
            float bv[4] = {rb.x, rb.y, rb.z, rb.w};
#pragma unroll
            for (int i = 0; i < 8; i++)
#pragma unroll
                for (int j = 0; j < 4; j++)
                    acc[i][j] += av[i] * bv[j];
        }
    }

    if (QKV) {
#pragma unroll
        for (int i = 0; i < 8; i++) {
            int m  = row0 + ty*8 + i;
            int b_ = m / NT, n_ = m - b_*NT;
#pragma unroll
            for (int j = 0; j < 4; j++) {
                int nn = col0 + tx*4 + j;
                int h  = nn / 96, c = nn - h*96;
                float val = acc[i][j] + bias[nn];
                size_t base = ((size_t)(b_*HH + h)*NT + n_);
                if      (c < KD)   g_q[base*KD + c]        = val;
                else if (c < 2*KD) g_k[base*KD + (c-KD)]   = val;
                else               g_v[base*VD + (c-2*KD)] = val;
            }
        }
    } else {
#pragma unroll
        for (int i = 0; i < 8; i++) {
            int m = row0 + ty*8 + i;
#pragma unroll
            for (int j = 0; j < 4; j++) {
                int nn = col0 + tx*4 + j;
                C[(size_t)m*DIM + nn] = acc[i][j] + bias[nn];
            }
        }
    }
}

// ---------------- kernel 3: attention, one block per (b,h) ---------------------
// smem layout (floats): Ksh[196*33] Vsh[196*33] absh[196] qsh[8*32] psh[8*208]
__global__ void __launch_bounds__(256) attn_kernel(const float* __restrict__ ab,
                                                   const int* __restrict__ bias_idxs) {
    extern __shared__ float sm[];
    float* Ksh  = sm;                      // 6468
    float* Vsh  = Ksh + NT*33;             // 6468
    float* absh = Vsh + NT*33;             // 196
    float* qsh  = absh + NT;               // 256
    float* psh  = qsh  + 8*32;             // 8*208

    int bh   = blockIdx.x;
    int b_   = bh / HH;
    int h    = bh - b_*HH;
    int tid  = threadIdx.x;
    int w    = tid >> 5;
    int lane = tid & 31;

    const float* kb = g_k + (size_t)bh * NT * KD;
    const float* vb = g_v + (size_t)bh * NT * VD;

    for (int i = tid; i < NT*KD; i += 256) {
        int m = i >> 5, d = i & 31;
        Ksh[m*33 + d] = kb[i];
        Vsh[m*33 + d] = vb[i];
    }
    for (int i = tid; i < NT; i += 256) absh[i] = ab[h*NT + i];
    __syncthreads();

    for (int n = w; n < NT; n += 8) {
        qsh[w*32 + lane] = g_q[((size_t)bh*NT + n)*KD + lane];
        __syncwarp();

        const int* bi = bias_idxs + n*NT;
        float s[7];
        float mx = -1e30f;
#pragma unroll
        for (int j = 0; j < 7; j++) {
            int m = lane + j*32;
            float sc = -1e30f;
            if (m < NT) {
                float a = 0.f;
#pragma unroll
                for (int d = 0; d < 32; d++) a += qsh[w*32 + d] * Ksh[m*33 + d];
                sc = a * QK_SCALE + absh[bi[m]];
            }
            s[j] = sc;
            mx = fmaxf(mx, sc);
        }
#pragma unroll
        for (int o = 16; o; o >>= 1) mx = fmaxf(mx, __shfl_xor_sync(0xffffffffu, mx, o));

        float sum = 0.f;
#pragma unroll
        for (int j = 0; j < 7; j++) {
            int m = lane + j*32;
            if (m < NT) { s[j] = __expf(s[j] - mx); sum += s[j]; }
            else s[j] = 0.f;
        }
#pragma unroll
        for (int o = 16; o; o >>= 1) sum += __shfl_xor_sync(0xffffffffu, sum, o);
        float inv = __fdividef(1.f, sum);

#pragma unroll
        for (int j = 0; j < 7; j++) {
            int m = lane + j*32;
            if (m < NT) psh[w*208 + m] = s[j] * inv;
        }
        __syncwarp();

        // AV: lane = vd
        float acc = 0.f;
        for (int m = 0; m < NT; m++) acc += psh[w*208 + m] * Vsh[m*33 + lane];
        g_att[((size_t)(b_*NT + n))*DIM + h*VD + lane] = acc;
    }
}

// ---------------- launch ------------------------------------------------------
extern "C" void kernel_launch(void* const* d_in, const int* in_sizes, int n_in,
                              void* d_out, int out_size) {
    const float* x      = (const float*)d_in[0];
    const float* norm_w = (const float*)d_in[1];
    const float* norm_b = (const float*)d_in[2];
    const float* qkv_w  = (const float*)d_in[3];
    const float* qkv_b  = (const float*)d_in[4];
    const float* attb   = (const float*)d_in[5];
    const float* proj_w = (const float*)d_in[6];
    const float* proj_b = (const float*)d_in[7];
    const int*   bidx   = (const int*)  d_in[8];
    float* out = (float*)d_out;

    // 60208 bytes dynamic smem for attention
    const int attn_smem = (NT*33*2 + NT + 8*32 + 8*208) * (int)sizeof(float);
    cudaFuncSetAttribute(attn_kernel, cudaFuncAttributeMaxDynamicSharedMemorySize, attn_smem);

    ln_kernel<<<MM/8, 256>>>(x, norm_w, norm_b);
    gemm_kernel<true ><<<dim3(MM/128, FF/64),  256>>>(qkv_w, qkv_b, nullptr);
    attn_kernel<<<BB*HH, 256, attn_smem>>>(attb, bidx);
    gemm_kernel<false><<<dim3(MM/128, DIM/64), 256>>>(proj_w, proj_b, out);
}

// round 2
// speedup vs baseline: 1.8515x; 1.8515x over previous
#include <cuda_runtime.h>
#include <stdint.h>
#include <math.h>

#define BB   256
#define NT   196
#define DIM  384
#define HH   12
#define KD   32
#define VD   32
#define MM   (BB*NT)          // 50176
#define FF   (HH*(2*KD+VD))   // 1152
#define QK_SCALE 0.17677669529663687f  // 32^-0.5

// ---------------- scratch (static device arrays; no cudaMalloc) ---------------
__device__ float g_xn [MM*DIM];          // layernorm output
__device__ float g_q  [BB*HH*NT*KD];     // [b][h][n][kd]
__device__ float g_k  [BB*HH*NT*KD];
__device__ float g_v  [BB*HH*NT*VD];
__device__ float g_att[MM*DIM];          // attention out [m][h*32+vd]

// ---------------- helpers -----------------------------------------------------
__device__ __forceinline__ uint32_t f2tf32(float f) {
    uint32_t u;
    asm("cvt.rna.tf32.f32 %0, %1;" : "=r"(u) : "f"(f));
    return u;
}
__device__ __forceinline__ void mma_tf32(float* c, const uint32_t* a, const uint32_t* b) {
    asm volatile(
        "mma.sync.aligned.m16n8k8.row.col.f32.tf32.tf32.f32 "
        "{%0,%1,%2,%3}, {%4,%5,%6,%7}, {%8,%9}, {%0,%1,%2,%3};"
        : "+f"(c[0]), "+f"(c[1]), "+f"(c[2]), "+f"(c[3])
        : "r"(a[0]), "r"(a[1]), "r"(a[2]), "r"(a[3]), "r"(b[0]), "r"(b[1]));
}

// ---------------- kernel 1: LayerNorm, one warp per row -----------------------
__global__ void __launch_bounds__(256) ln_kernel(const float* __restrict__ x,
                                                 const float* __restrict__ w,
                                                 const float* __restrict__ b) {
    int row  = blockIdx.x * 8 + (threadIdx.x >> 5);
    int lane = threadIdx.x & 31;
    const float* xr = x + (size_t)row * DIM;
    float4 v[3];
    float sum = 0.f, sq = 0.f;
#pragma unroll
    for (int j = 0; j < 3; j++) {
        v[j] = *(const float4*)(xr + j*128 + lane*4);
        sum += v[j].x + v[j].y + v[j].z + v[j].w;
        sq  += v[j].x*v[j].x + v[j].y*v[j].y + v[j].z*v[j].z + v[j].w*v[j].w;
    }
#pragma unroll
    for (int o = 16; o; o >>= 1) {
        sum += __shfl_xor_sync(0xffffffffu, sum, o);
        sq  += __shfl_xor_sync(0xffffffffu, sq,  o);
    }
    float mean = sum * (1.f/DIM);
    float var  = sq  * (1.f/DIM) - mean*mean;
    float inv  = rsqrtf(var + 1e-5f);
    float* orow = g_xn + (size_t)row * DIM;
#pragma unroll
    for (int j = 0; j < 3; j++) {
        float4 ww = *(const float4*)(w + j*128 + lane*4);
        float4 bb = *(const float4*)(b + j*128 + lane*4);
        float4 o4;
        o4.x = (v[j].x - mean)*inv*ww.x + bb.x;
        o4.y = (v[j].y - mean)*inv*ww.y + bb.y;
        o4.z = (v[j].z - mean)*inv*ww.z + bb.z;
        o4.w = (v[j].w - mean)*inv*ww.w + bb.w;
        *(float4*)(orow + j*128 + lane*4) = o4;
    }
}

// ---------------- kernel 2/4: TF32 tensor-core GEMM ---------------------------
// C[m][nn] = sum_k A[m][k] * W[nn][k] + bias[nn]
// Block tile 128(m) x 64(n), k-tile 32. 8 warps: warp grid 4(m) x 2(n), each 32x32.
// blockIdx.x = n-tile (fast-varying -> A tile reused via L2), blockIdx.y = m-tile.
template<bool QKV>
__global__ void __launch_bounds__(256) gemm_tf32(const float* __restrict__ W,
                                                 const float* __restrict__ bias,
                                                 float* __restrict__ C) {
    __shared__ uint32_t As[128][36];   // m-major, tf32 bits, pad 36 -> conflict-free
    __shared__ uint32_t Bs[64][36];
    const float* A = QKV ? g_xn : g_att;

    int tid  = threadIdx.x;
    int wid  = tid >> 5, lane = tid & 31;
    int warp_m = (wid >> 1) * 32;      // 0,32,64,96
    int warp_n = (wid & 1) * 32;       // 0,32
    int col0 = blockIdx.x * 64;
    int row0 = blockIdx.y * 128;

    int la_c = tid & 7;                // float4 column within 32-wide k-tile
    int la_r = tid >> 3;               // 0..31
    const float* Ag = A + (size_t)(row0 + la_r) * DIM + la_c * 4;
    const float* Wg = W + (size_t)(col0 + la_r) * DIM + la_c * 4;

    float acc[2][4][4];
#pragma unroll
    for (int i = 0; i < 2; i++)
#pragma unroll
        for (int j = 0; j < 4; j++)
#pragma unroll
            for (int k = 0; k < 4; k++) acc[i][j][k] = 0.f;

    for (int kt = 0; kt < DIM; kt += 32) {
        float4 av[4], bv[2];
#pragma unroll
        for (int it = 0; it < 4; it++)
            av[it] = *(const float4*)(Ag + (size_t)it*32*DIM + kt);
        bv[0] = *(const float4*)(Wg + kt);
        bv[1] = *(const float4*)(Wg + (size_t)32*DIM + kt);
        __syncthreads();
#pragma unroll
        for (int it = 0; it < 4; it++) {
            int r = la_r + it*32;
            uint4 t;
            t.x = f2tf32(av[it].x); t.y = f2tf32(av[it].y);
            t.z = f2tf32(av[it].z); t.w = f2tf32(av[it].w);
            *(uint4*)&As[r][la_c*4] = t;
        }
        {
            uint4 t;
            t.x = f2tf32(bv[0].x); t.y = f2tf32(bv[0].y);
            t.z = f2tf32(bv[0].z); t.w = f2tf32(bv[0].w);
            *(uint4*)&Bs[la_r][la_c*4] = t;
            t.x = f2tf32(bv[1].x); t.y = f2tf32(bv[1].y);
            t.z = f2tf32(bv[1].z); t.w = f2tf32(bv[1].w);
            *(uint4*)&Bs[la_r + 32][la_c*4] = t;
        }
        __syncthreads();
#pragma unroll
        for (int ks = 0; ks < 32; ks += 8) {
            uint32_t afr[2][4], bfr[4][2];
            int kk = ks + (lane & 3);
#pragma unroll
            for (int mt = 0; mt < 2; mt++) {
                int r0 = warp_m + mt*16 + (lane >> 2);
                afr[mt][0] = As[r0    ][kk];
                afr[mt][1] = As[r0 + 8][kk];
                afr[mt][2] = As[r0    ][kk + 4];
                afr[mt][3] = As[r0 + 8][kk + 4];
            }
#pragma unroll
            for (int nt = 0; nt < 4; nt++) {
                int c0 = warp_n + nt*8 + (lane >> 2);
                bfr[nt][0] = Bs[c0][kk];
                bfr[nt][1] = Bs[c0][kk + 4];
            }
#pragma unroll
            for (int mt = 0; mt < 2; mt++)
#pragma unroll
                for (int nt = 0; nt < 4; nt++)
                    mma_tf32(acc[mt][nt], afr[mt], bfr[nt]);
        }
    }

    // epilogue: c[i] mapping -> row += (i>=2)*8, col += (i&1)
#pragma unroll
    for (int mt = 0; mt < 2; mt++) {
#pragma unroll
        for (int nt = 0; nt < 4; nt++) {
#pragma unroll
            for (int i = 0; i < 4; i++) {
                int row = warp_m + mt*16 + (lane >> 2) + ((i >> 1) * 8);
                int col = warp_n + nt*8 + (lane & 3)*2 + (i & 1);
                int m  = row0 + row;
                int nn = col0 + col;
                float val = acc[mt][nt][i] + bias[nn];
                if (QKV) {
                    int b_ = m / NT, n_ = m - b_*NT;
                    int h  = nn / 96, c = nn - h*96;
                    size_t base = ((size_t)(b_*HH + h)*NT + n_);
                    if      (c < KD)   g_q[base*KD + c]        = val;
                    else if (c < 2*KD) g_k[base*KD + (c-KD)]   = val;
                    else               g_v[base*VD + (c-2*KD)] = val;
                } else {
                    C[(size_t)m*DIM + nn] = val;
                }
            }
        }
    }
}

// ---------------- kernel 3: attention, one block per (b,h) ---------------------
// Each warp processes 4 query rows at once -> K/V smem traffic amortized 4x.
// All smem reads are float4 and conflict-free (K pad 36, V transposed pad 204).
__global__ void __launch_bounds__(256) attn_kernel(const float* __restrict__ ab,
                                                   const int* __restrict__ bias_idxs) {
    extern __shared__ float sm[];
    float* Ksh  = sm;                    // 196*36 = 7056 floats, [m][d] pad36
    float* Vt   = Ksh + NT*36;           // 32*204 = 6528 floats, [d][m] pad204
    float* absh = Vt + 32*204;           // 196
    float* qsh  = absh + NT;             // 8*128
    float* psh  = qsh + 8*128;           // 8*4*196

    int bh = blockIdx.x;
    int b_ = bh / HH;
    int h  = bh - b_*HH;
    int tid = threadIdx.x, w = tid >> 5, lane = tid & 31;

    const float4* kg = (const float4*)(g_k + (size_t)bh * NT * KD);
    const float4* vg = (const float4*)(g_v + (size_t)bh * NT * VD);
    for (int f = tid; f < NT*8; f += 256) {
        int m = f >> 3, d4 = f & 7;
        ((float4*)Ksh)[m*9 + d4] = kg[f];
        float4 v4 = vg[f];
        int d0 = d4 * 4;
        Vt[(d0+0)*204 + m] = v4.x;
        Vt[(d0+1)*204 + m] = v4.y;
        Vt[(d0+2)*204 + m] = v4.z;
        Vt[(d0+3)*204 + m] = v4.w;
    }
    for (int i = tid; i < NT; i += 256) absh[i] = ab[h*NT + i];
    __syncthreads();

    const float4* Ksh4 = (const float4*)Ksh;

    for (int g = w; g < 49; g += 8) {          // 49 groups of 4 rows = 196
        int n0 = g * 4;
#pragma unroll
        for (int r = 0; r < 4; r++)
            qsh[w*128 + r*32 + lane] = g_q[((size_t)bh*NT + n0 + r)*KD + lane];
        __syncwarp();

        const float4* q4p = (const float4*)(qsh + w*128);
        float s[4][7];
#pragma unroll
        for (int j = 0; j < 7; j++) {
            int m = lane + j*32;
            if (m < NT) {
                float a0=0.f, a1=0.f, a2=0.f, a3=0.f;
#pragma unroll
                for (int d4 = 0; d4 < 8; d4++) {
                    float4 k4 = Ksh4[m*9 + d4];
                    float4 qa = q4p[0*8 + d4];
                    float4 qb = q4p[1*8 + d4];
                    float4 qc = q4p[2*8 + d4];
                    float4 qd = q4p[3*8 + d4];
                    a0 += qa.x*k4.x + qa.y*k4.y + qa.z*k4.z + qa.w*k4.w;
                    a1 += qb.x*k4.x + qb.y*k4.y + qb.z*k4.z + qb.w*k4.w;
                    a2 += qc.x*k4.x + qc.y*k4.y + qc.z*k4.z + qc.w*k4.w;
                    a3 += qd.x*k4.x + qd.y*k4.y + qd.z*k4.z + qd.w*k4.w;
                }
                s[0][j] = a0*QK_SCALE + absh[bias_idxs[(n0+0)*NT + m]];
                s[1][j] = a1*QK_SCALE + absh[bias_idxs[(n0+1)*NT + m]];
                s[2][j] = a2*QK_SCALE + absh[bias_idxs[(n0+2)*NT + m]];
                s[3][j] = a3*QK_SCALE + absh[bias_idxs[(n0+3)*NT + m]];
            } else {
                s[0][j] = -1e30f; s[1][j] = -1e30f; s[2][j] = -1e30f; s[3][j] = -1e30f;
            }
        }

#pragma unroll
        for (int r = 0; r < 4; r++) {
            float mx = -1e30f;
#pragma unroll
            for (int j = 0; j < 7; j++) mx = fmaxf(mx, s[r][j]);
#pragma unroll
            for (int o = 16; o; o >>= 1) mx = fmaxf(mx, __shfl_xor_sync(0xffffffffu, mx, o));
            float sum = 0.f;
#pragma unroll
            for (int j = 0; j < 7; j++) {
                int m = lane + j*32;
                if (m < NT) { s[r][j] = __expf(s[r][j] - mx); sum += s[r][j]; }
                else s[r][j] = 0.f;
            }
#pragma unroll
            for (int o = 16; o; o >>= 1) sum += __shfl_xor_sync(0xffffffffu, sum, o);
            float inv = __fdividef(1.f, sum);
#pragma unroll
            for (int j = 0; j < 7; j++) {
                int m = lane + j*32;
                if (m < NT) psh[(w*4 + r)*NT + m] = s[r][j] * inv;
            }
        }
        __syncwarp();

        // AV: lane = vd; V transposed, conflict-free float4 reads
        float acc0=0.f, acc1=0.f, acc2=0.f, acc3=0.f;
        const float4* Vt4 = (const float4*)(Vt + lane*204);
        const float4* p0p = (const float4*)(psh + (w*4 + 0)*NT);
        const float4* p1p = (const float4*)(psh + (w*4 + 1)*NT);
        const float4* p2p = (const float4*)(psh + (w*4 + 2)*NT);
        const float4* p3p = (const float4*)(psh + (w*4 + 3)*NT);
#pragma unroll 7
        for (int m4 = 0; m4 < 49; m4++) {
            float4 v4 = Vt4[m4];
            float4 p0 = p0p[m4], p1 = p1p[m4], p2 = p2p[m4], p3 = p3p[m4];
            acc0 += p0.x*v4.x + p0.y*v4.y + p0.z*v4.z + p0.w*v4.w;
            acc1 += p1.x*v4.x + p1.y*v4.y + p1.z*v4.z + p1.w*v4.w;
            acc2 += p2.x*v4.x + p2.y*v4.y + p2.z*v4.z + p2.w*v4.w;
            acc3 += p3.x*v4.x + p3.y*v4.y + p3.z*v4.z + p3.w*v4.w;
        }
        g_att[((size_t)(b_*NT + n0+0))*DIM + h*VD + lane] = acc0;
        g_att[((size_t)(b_*NT + n0+1))*DIM + h*VD + lane] = acc1;
        g_att[((size_t)(b_*NT + n0+2))*DIM + h*VD + lane] = acc2;
        g_att[((size_t)(b_*NT + n0+3))*DIM + h*VD + lane] = acc3;
    }
}

// ---------------- launch ------------------------------------------------------
extern "C" void kernel_launch(void* const* d_in, const int* in_sizes, int n_in,
                              void* d_out, int out_size) {
    const float* x      = (const float*)d_in[0];
    const float* norm_w = (const float*)d_in[1];
    const float* norm_b = (const float*)d_in[2];
    const float* qkv_w  = (const float*)d_in[3];
    const float* qkv_b  = (const float*)d_in[4];
    const float* attb   = (const float*)d_in[5];
    const float* proj_w = (const float*)d_in[6];
    const float* proj_b = (const float*)d_in[7];
    const int*   bidx   = (const int*)  d_in[8];
    float* out = (float*)d_out;

    const int attn_smem = (NT*36 + 32*204 + NT + 8*128 + 8*4*NT) * (int)sizeof(float);
    cudaFuncSetAttribute(attn_kernel, cudaFuncAttributeMaxDynamicSharedMemorySize, attn_smem);

    ln_kernel<<<MM/8, 256>>>(x, norm_w, norm_b);
    gemm_tf32<true ><<<dim3(FF/64,  MM/128), 256>>>(qkv_w, qkv_b, nullptr);
    attn_kernel<<<BB*HH, 256, attn_smem>>>(attb, bidx);
    gemm_tf32<false><<<dim3(DIM/64, MM/128), 256>>>(proj_w, proj_b, out);
}

// round 3
// speedup vs baseline: 3.0485x; 1.6465x over previous
#include <cuda_runtime.h>
#include <stdint.h>
#include <math.h>

#define BB   256
#define NT   196
#define NP   208              // NT padded to 13*16
#define DIM  384
#define HH   12
#define KD   32
#define VD   32
#define MM   (BB*NT)          // 50176
#define FF   (HH*(2*KD+VD))   // 1152
#define QK_SCALE 0.17677669529663687f  // 32^-0.5

// ---------------- scratch (static device arrays; no cudaMalloc) ---------------
__device__ float g_xn [MM*DIM];          // layernorm output
__device__ float g_q  [BB*HH*NT*KD];     // [b][h][n][kd]
__device__ float g_k  [BB*HH*NT*KD];
__device__ float g_v  [BB*HH*NT*VD];
__device__ float g_att[MM*DIM];          // attention out [m][h*32+vd]
__device__ float g_b  [HH*NP*NP];        // expanded bias, pad = -1e30

// ---------------- helpers -----------------------------------------------------
__device__ __forceinline__ uint32_t f2tf32(float f) {
    uint32_t u;
    asm("cvt.rna.tf32.f32 %0, %1;" : "=r"(u) : "f"(f));
    return u;
}
__device__ __forceinline__ void mma_tf32(float* c, const uint32_t* a, const uint32_t* b) {
    asm volatile(
        "mma.sync.aligned.m16n8k8.row.col.f32.tf32.tf32.f32 "
        "{%0,%1,%2,%3}, {%4,%5,%6,%7}, {%8,%9}, {%0,%1,%2,%3};"
        : "+f"(c[0]), "+f"(c[1]), "+f"(c[2]), "+f"(c[3])
        : "r"(a[0]), "r"(a[1]), "r"(a[2]), "r"(a[3]), "r"(b[0]), "r"(b[1]));
}
__device__ __forceinline__ void cp_async16(uint32_t saddr, const void* gptr) {
    asm volatile("cp.async.ca.shared.global [%0], [%1], 16;\n" :: "r"(saddr), "l"(gptr));
}

// ---------------- kernel 1: LayerNorm, one warp per row -----------------------
__global__ void __launch_bounds__(256) ln_kernel(const float* __restrict__ x,
                                                 const float* __restrict__ w,
                                                 const float* __restrict__ b) {
    int row  = blockIdx.x * 8 + (threadIdx.x >> 5);
    int lane = threadIdx.x & 31;
    const float* xr = x + (size_t)row * DIM;
    float4 v[3];
    float sum = 0.f, sq = 0.f;
#pragma unroll
    for (int j = 0; j < 3; j++) {
        v[j] = *(const float4*)(xr + j*128 + lane*4);
        sum += v[j].x + v[j].y + v[j].z + v[j].w;
        sq  += v[j].x*v[j].x + v[j].y*v[j].y + v[j].z*v[j].z + v[j].w*v[j].w;
    }
#pragma unroll
    for (int o = 16; o; o >>= 1) {
        sum += __shfl_xor_sync(0xffffffffu, sum, o);
        sq  += __shfl_xor_sync(0xffffffffu, sq,  o);
    }
    float mean = sum * (1.f/DIM);
    float var  = sq  * (1.f/DIM) - mean*mean;
    float inv  = rsqrtf(var + 1e-5f);
    float* orow = g_xn + (size_t)row * DIM;
#pragma unroll
    for (int j = 0; j < 3; j++) {
        float4 ww = *(const float4*)(w + j*128 + lane*4);
        float4 bb = *(const float4*)(b + j*128 + lane*4);
        float4 o4;
        o4.x = (v[j].x - mean)*inv*ww.x + bb.x;
        o4.y = (v[j].y - mean)*inv*ww.y + bb.y;
        o4.z = (v[j].z - mean)*inv*ww.z + bb.z;
        o4.w = (v[j].w - mean)*inv*ww.w + bb.w;
        *(float4*)(orow + j*128 + lane*4) = o4;
    }
}

// ---------------- bias expansion: gb[h][n][m] ---------------------------------
__global__ void bias_expand(const float* __restrict__ ab, const int* __restrict__ bidx) {
    int n = blockIdx.x, h = blockIdx.y, m = threadIdx.x;
    float v = -1e30f;
    if (n < NT && m < NT) v = ab[h*NT + bidx[n*NT + m]];
    g_b[((size_t)h*NP + n)*NP + m] = v;
}

// ---------------- kernel 2/4: TF32 GEMM, 128x128, cp.async double-buffered ----
// C[m][nn] = sum_k A[m][k] * W[nn][k] + bias[nn]
template<bool QKV>
__global__ void __launch_bounds__(256) gemm_tf32(const float* __restrict__ W,
                                                 const float* __restrict__ bias,
                                                 float* __restrict__ C) {
    extern __shared__ float sm[];
    float* As = sm;                 // [2][128][36]
    float* Bs = sm + 2*128*36;      // [2][128][36]
    const float* A = QKV ? g_xn : g_att;

    int tid  = threadIdx.x;
    int wid  = tid >> 5, lane = tid & 31;
    int warp_m = (wid >> 1) * 32;   // 0,32,64,96
    int warp_n = (wid & 1) * 64;    // 0,64
    int col0 = blockIdx.x * 128;
    int row0 = blockIdx.y * 128;

    int lr = tid >> 3;              // 0..31
    int lc = tid & 7;               // float4 slot in 32-wide k-tile
    uint32_t sA = (uint32_t)__cvta_generic_to_shared(As);
    uint32_t sB = (uint32_t)__cvta_generic_to_shared(Bs);

    float acc[2][8][4];
#pragma unroll
    for (int i = 0; i < 2; i++)
#pragma unroll
        for (int j = 0; j < 8; j++)
#pragma unroll
            for (int k = 0; k < 4; k++) acc[i][j][k] = 0.f;

    auto load_stage = [&](int st, int kt) {
#pragma unroll
        for (int it = 0; it < 4; it++) {
            int r = lr + it*32;
            cp_async16(sA + ((st*128 + r)*36 + lc*4)*4,
                       A + (size_t)(row0 + r)*DIM + kt + lc*4);
            cp_async16(sB + ((st*128 + r)*36 + lc*4)*4,
                       W + (size_t)(col0 + r)*DIM + kt + lc*4);
        }
    };

    const int T = DIM / 32;         // 12
    load_stage(0, 0);
    asm volatile("cp.async.commit_group;\n" ::);

    for (int t = 0; t < T; t++) {
        if (t + 1 < T) {
            load_stage((t+1)&1, (t+1)*32);
            asm volatile("cp.async.commit_group;\n" ::);
            asm volatile("cp.async.wait_group 1;\n" ::);
        } else {
            asm volatile("cp.async.wait_group 0;\n" ::);
        }
        __syncthreads();
        int st = t & 1;
        const float* Ab = As + st*128*36;
        const float* Bb = Bs + st*128*36;
#pragma unroll
        for (int ks = 0; ks < 4; ks++) {
            int kq = ks*8 + (lane & 3);
            uint32_t af[2][4], bf[8][2];
#pragma unroll
            for (int mt = 0; mt < 2; mt++) {
                int r = warp_m + mt*16 + (lane >> 2);
                af[mt][0] = f2tf32(Ab[(r   )*36 + kq]);
                af[mt][1] = f2tf32(Ab[(r+8 )*36 + kq]);
                af[mt][2] = f2tf32(Ab[(r   )*36 + kq+4]);
                af[mt][3] = f2tf32(Ab[(r+8 )*36 + kq+4]);
            }
#pragma unroll
            for (int nt = 0; nt < 8; nt++) {
                int c = warp_n + nt*8 + (lane >> 2);
                bf[nt][0] = f2tf32(Bb[c*36 + kq]);
                bf[nt][1] = f2tf32(Bb[c*36 + kq+4]);
            }
#pragma unroll
            for (int mt = 0; mt < 2; mt++)
#pragma unroll
                for (int nt = 0; nt < 8; nt++)
                    mma_tf32(acc[mt][nt], af[mt], bf[nt]);
        }
        __syncthreads();
    }

#pragma unroll
    for (int mt = 0; mt < 2; mt++) {
#pragma unroll
        for (int nt = 0; nt < 8; nt++) {
#pragma unroll
            for (int i = 0; i < 4; i++) {
                int m  = row0 + warp_m + mt*16 + (lane >> 2) + ((i >> 1) * 8);
                int nn = col0 + warp_n + nt*8 + (lane & 3)*2 + (i & 1);
                float val = acc[mt][nt][i] + bias[nn];
                if (QKV) {
                    int b_ = m / NT, n_ = m - b_*NT;
                    int h  = nn / 96, c = nn - h*96;
                    size_t base = ((size_t)(b_*HH + h)*NT + n_);
                    if      (c < KD)   g_q[base*KD + c]        = val;
                    else if (c < 2*KD) g_k[base*KD + (c-KD)]   = val;
                    else               g_v[base*VD + (c-2*KD)] = val;
                } else {
                    C[(size_t)m*DIM + nn] = val;
                }
            }
        }
    }
}

// ---------------- kernel 3: tensor-core attention, one block per (b,h) --------
// 7 warps; warp w handles 16-row Q tiles {w, w+7}. S rows kept in registers,
// P reused as mma A-fragments via V-row permutation (no smem round-trip).
#define VT_PITCH 212
__global__ void __launch_bounds__(224) attn_mma() {
    extern __shared__ uint32_t smu[];
    uint32_t* Ksh = smu;                 // [208][36] tf32 bits
    uint32_t* Vt  = smu + NP*36;         // [32][212] tf32 bits, token-permuted

    int bh = blockIdx.x;
    int b_ = bh / HH;
    int h  = bh - b_*HH;
    int tid = threadIdx.x, w = tid >> 5, lane = tid & 31;

    // load K (tf32) and V (tf32, transposed + permuted)
    for (int i = tid; i < NP*8; i += 224) {
        int m = i >> 3, c4 = i & 7;
        float4 kv = {0.f,0.f,0.f,0.f};
        if (m < NT) kv = *(const float4*)(g_k + ((size_t)bh*NT + m)*KD + c4*4);
        uint4 t;
        t.x = f2tf32(kv.x); t.y = f2tf32(kv.y); t.z = f2tf32(kv.z); t.w = f2tf32(kv.w);
        *(uint4*)&Ksh[m*36 + c4*4] = t;

        int p = m;                                   // V smem slot
        int tok = (p & ~7) + 2*(p & 3) + ((p >> 2) & 1);
        float4 vv = {0.f,0.f,0.f,0.f};
        if (tok < NT) vv = *(const float4*)(g_v + ((size_t)bh*NT + tok)*VD + c4*4);
        Vt[(c4*4+0)*VT_PITCH + p] = f2tf32(vv.x);
        Vt[(c4*4+1)*VT_PITCH + p] = f2tf32(vv.y);
        Vt[(c4*4+2)*VT_PITCH + p] = f2tf32(vv.z);
        Vt[(c4*4+3)*VT_PITCH + p] = f2tf32(vv.w);
    }
    __syncthreads();

    for (int iter = 0; iter < 2; iter++) {
        int tile = w + iter*7;
        if (tile >= 13) break;
        int r0 = tile*16 + (lane >> 2);
        int r1 = r0 + 8;

        // Q A-fragments (scale folded in)
        uint32_t qa[4][4];
#pragma unroll
        for (int kt = 0; kt < 4; kt++) {
            int k0 = kt*8 + (lane & 3);
            float q00 = (r0 < NT) ? g_q[((size_t)bh*NT + r0)*KD + k0    ] * QK_SCALE : 0.f;
            float q10 = (r1 < NT) ? g_q[((size_t)bh*NT + r1)*KD + k0    ] * QK_SCALE : 0.f;
            float q01 = (r0 < NT) ? g_q[((size_t)bh*NT + r0)*KD + k0 + 4] * QK_SCALE : 0.f;
            float q11 = (r1 < NT) ? g_q[((size_t)bh*NT + r1)*KD + k0 + 4] * QK_SCALE : 0.f;
            qa[kt][0] = f2tf32(q00); qa[kt][1] = f2tf32(q10);
            qa[kt][2] = f2tf32(q01); qa[kt][3] = f2tf32(q11);
        }

        // S = Q K^T
        float s[26][4];
#pragma unroll
        for (int nt = 0; nt < 26; nt++) { s[nt][0]=0.f; s[nt][1]=0.f; s[nt][2]=0.f; s[nt][3]=0.f; }
#pragma unroll
        for (int nt = 0; nt < 26; nt++) {
            int c = nt*8 + (lane >> 2);
#pragma unroll
            for (int kt = 0; kt < 4; kt++) {
                uint32_t bfr[2];
                bfr[0] = Ksh[c*36 + kt*8 + (lane & 3)];
                bfr[1] = Ksh[c*36 + kt*8 + (lane & 3) + 4];
                mma_tf32(s[nt], qa[kt], bfr);
            }
        }

        // + bias (fp32, from expanded table)
        const float* gbh = g_b + (size_t)h*NP*NP;
#pragma unroll
        for (int nt = 0; nt < 26; nt++) {
            int c = nt*8 + 2*(lane & 3);
            float2 b0 = *(const float2*)(gbh + (size_t)r0*NP + c);
            float2 b1 = *(const float2*)(gbh + (size_t)r1*NP + c);
            s[nt][0] += b0.x; s[nt][1] += b0.y;
            s[nt][2] += b1.x; s[nt][3] += b1.y;
        }

        // softmax (rows r0, r1)
        float mx0 = -1e30f, mx1 = -1e30f;
#pragma unroll
        for (int nt = 0; nt < 26; nt++) {
            mx0 = fmaxf(mx0, fmaxf(s[nt][0], s[nt][1]));
            mx1 = fmaxf(mx1, fmaxf(s[nt][2], s[nt][3]));
        }
        mx0 = fmaxf(mx0, __shfl_xor_sync(0xffffffffu, mx0, 1));
        mx0 = fmaxf(mx0, __shfl_xor_sync(0xffffffffu, mx0, 2));
        mx1 = fmaxf(mx1, __shfl_xor_sync(0xffffffffu, mx1, 1));
        mx1 = fmaxf(mx1, __shfl_xor_sync(0xffffffffu, mx1, 2));
        float sum0 = 0.f, sum1 = 0.f;
#pragma unroll
        for (int nt = 0; nt < 26; nt++) {
            s[nt][0] = __expf(s[nt][0] - mx0); sum0 += s[nt][0];
            s[nt][1] = __expf(s[nt][1] - mx0); sum0 += s[nt][1];
            s[nt][2] = __expf(s[nt][2] - mx1); sum1 += s[nt][2];
            s[nt][3] = __expf(s[nt][3] - mx1); sum1 += s[nt][3];
        }
        sum0 += __shfl_xor_sync(0xffffffffu, sum0, 1);
        sum0 += __shfl_xor_sync(0xffffffffu, sum0, 2);
        sum1 += __shfl_xor_sync(0xffffffffu, sum1, 1);
        sum1 += __shfl_xor_sync(0xffffffffu, sum1, 2);
        float inv0 = __fdividef(1.f, sum0);
        float inv1 = __fdividef(1.f, sum1);

        // O = P V  (P C-frag -> A-frag via V permutation: a = {c0,c2,c1,c3})
        float o[4][4];
#pragma unroll
        for (int vt = 0; vt < 4; vt++) { o[vt][0]=0.f; o[vt][1]=0.f; o[vt][2]=0.f; o[vt][3]=0.f; }
#pragma unroll
        for (int kt = 0; kt < 26; kt++) {
            uint32_t pa[4];
            pa[0] = f2tf32(s[kt][0]);
            pa[1] = f2tf32(s[kt][2]);
            pa[2] = f2tf32(s[kt][1]);
            pa[3] = f2tf32(s[kt][3]);
#pragma unroll
            for (int vt = 0; vt < 4; vt++) {
                uint32_t bfr[2];
                int d = vt*8 + (lane >> 2);
                bfr[0] = Vt[d*VT_PITCH + kt*8 + (lane & 3)];
                bfr[1] = Vt[d*VT_PITCH + kt*8 + (lane & 3) + 4];
                mma_tf32(o[vt], pa, bfr);
            }
        }

        // store (scaled by 1/sum)
        if (r0 < NT) {
            float* orow = g_att + ((size_t)(b_*NT + r0))*DIM + h*VD;
#pragma unroll
            for (int vt = 0; vt < 4; vt++) {
                float2 v2 = {o[vt][0]*inv0, o[vt][1]*inv0};
                *(float2*)(orow + vt*8 + 2*(lane & 3)) = v2;
            }
        }
        if (r1 < NT) {
            float* orow = g_att + ((size_t)(b_*NT + r1))*DIM + h*VD;
#pragma unroll
            for (int vt = 0; vt < 4; vt++) {
                float2 v2 = {o[vt][2]*inv1, o[vt][3]*inv1};
                *(float2*)(orow + vt*8 + 2*(lane & 3)) = v2;
            }
        }
    }
}

// ---------------- launch ------------------------------------------------------
extern "C" void kernel_launch(void* const* d_in, const int* in_sizes, int n_in,
                              void* d_out, int out_size) {
    const float* x      = (const float*)d_in[0];
    const float* norm_w = (const float*)d_in[1];
    const float* norm_b = (const float*)d_in[2];
    const float* qkv_w  = (const float*)d_in[3];
    const float* qkv_b  = (const float*)d_in[4];
    const float* attb   = (const float*)d_in[5];
    const float* proj_w = (const float*)d_in[6];
    const float* proj_b = (const float*)d_in[7];
    const int*   bidx   = (const int*)  d_in[8];
    float* out = (float*)d_out;

    const int gemm_smem = 2 * 2 * 128 * 36 * (int)sizeof(float);   // 73728
    const int attn_smem = (NP*36 + 32*VT_PITCH) * (int)sizeof(uint32_t); // 57088
    cudaFuncSetAttribute(gemm_tf32<true >, cudaFuncAttributeMaxDynamicSharedMemorySize, gemm_smem);
    cudaFuncSetAttribute(gemm_tf32<false>, cudaFuncAttributeMaxDynamicSharedMemorySize, gemm_smem);
    cudaFuncSetAttribute(attn_mma,         cudaFuncAttributeMaxDynamicSharedMemorySize, attn_smem);

    ln_kernel<<<MM/8, 256>>>(x, norm_w, norm_b);
    bias_expand<<<dim3(NP, HH), NP>>>(attb, bidx);
    gemm_tf32<true ><<<dim3(FF/128,  MM/128), 256, gemm_smem>>>(qkv_w, qkv_b, nullptr);
    attn_mma<<<BB*HH, 224, attn_smem>>>();
    gemm_tf32<false><<<dim3(DIM/128, MM/128), 256, gemm_smem>>>(proj_w, proj_b, out);
}

// round 4
// speedup vs baseline: 3.8496x; 1.2628x over previous
#include <cuda_runtime.h>
#include <stdint.h>
#include <math.h>

#define BB   256
#define NT   196
#define NP   208              // NT padded to 13*16
#define DIM  384
#define HH   12
#define KD   32
#define VD   32
#define MM   (BB*NT)          // 50176
#define FF   (HH*(2*KD+VD))   // 1152
#define QK_SCALE 0.17677669529663687f  // 32^-0.5

// ---------------- scratch (static device arrays; no cudaMalloc) ---------------
__device__ uint32_t g_xn   [MM*DIM];        // LN output, tf32 bits
__device__ uint32_t g_q32  [BB*HH*NT*KD];   // q*scale, tf32 bits
__device__ uint32_t g_k32  [BB*HH*NT*KD];
__device__ uint32_t g_v32  [BB*HH*NT*VD];
__device__ uint32_t g_att32[MM*DIM];        // attention out, tf32 bits
__device__ float    g_b    [HH*NP*NP];      // expanded bias, pad = -1e30
__device__ uint32_t g_qkvw32 [FF*DIM];      // weights, tf32 bits
__device__ uint32_t g_projw32[DIM*DIM];

// ---------------- helpers -----------------------------------------------------
__device__ __forceinline__ uint32_t f2tf32(float f) {
    uint32_t u;
    asm("cvt.rna.tf32.f32 %0, %1;" : "=r"(u) : "f"(f));
    return u;
}
__device__ __forceinline__ void mma_tf32(float* c, const uint32_t* a, const uint32_t* b) {
    asm volatile(
        "mma.sync.aligned.m16n8k8.row.col.f32.tf32.tf32.f32 "
        "{%0,%1,%2,%3}, {%4,%5,%6,%7}, {%8,%9}, {%0,%1,%2,%3};"
        : "+f"(c[0]), "+f"(c[1]), "+f"(c[2]), "+f"(c[3])
        : "r"(a[0]), "r"(a[1]), "r"(a[2]), "r"(a[3]), "r"(b[0]), "r"(b[1]));
}
__device__ __forceinline__ void cp_async16(uint32_t saddr, const void* gptr) {
    asm volatile("cp.async.ca.shared.global [%0], [%1], 16;\n" :: "r"(saddr), "l"(gptr));
}

// ---------------- kernel 0: convert weights to tf32 bits ----------------------
__global__ void cvt_tf32_kernel(const float* __restrict__ in, uint32_t* __restrict__ out, int n) {
    int i = blockIdx.x * 256 + threadIdx.x;
    if (i < n) out[i] = f2tf32(in[i]);
}

// ---------------- kernel 1: LayerNorm -> tf32 bits ----------------------------
__global__ void __launch_bounds__(256) ln_kernel(const float* __restrict__ x,
                                                 const float* __restrict__ w,
                                                 const float* __restrict__ b) {
    int row  = blockIdx.x * 8 + (threadIdx.x >> 5);
    int lane = threadIdx.x & 31;
    const float* xr = x + (size_t)row * DIM;
    float4 v[3];
    float sum = 0.f, sq = 0.f;
#pragma unroll
    for (int j = 0; j < 3; j++) {
        v[j] = *(const float4*)(xr + j*128 + lane*4);
        sum += v[j].x + v[j].y + v[j].z + v[j].w;
        sq  += v[j].x*v[j].x + v[j].y*v[j].y + v[j].z*v[j].z + v[j].w*v[j].w;
    }
#pragma unroll
    for (int o = 16; o; o >>= 1) {
        sum += __shfl_xor_sync(0xffffffffu, sum, o);
        sq  += __shfl_xor_sync(0xffffffffu, sq,  o);
    }
    float mean = sum * (1.f/DIM);
    float var  = sq  * (1.f/DIM) - mean*mean;
    float inv  = rsqrtf(var + 1e-5f);
    uint32_t* orow = g_xn + (size_t)row * DIM;
#pragma unroll
    for (int j = 0; j < 3; j++) {
        float4 ww = *(const float4*)(w + j*128 + lane*4);
        float4 bb = *(const float4*)(b + j*128 + lane*4);
        uint4 o4;
        o4.x = f2tf32((v[j].x - mean)*inv*ww.x + bb.x);
        o4.y = f2tf32((v[j].y - mean)*inv*ww.y + bb.y);
        o4.z = f2tf32((v[j].z - mean)*inv*ww.z + bb.z);
        o4.w = f2tf32((v[j].w - mean)*inv*ww.w + bb.w);
        *(uint4*)(orow + j*128 + lane*4) = o4;
    }
}

// ---------------- bias expansion: gb[h][n][m] ---------------------------------
__global__ void bias_expand(const float* __restrict__ ab, const int* __restrict__ bidx) {
    int n = blockIdx.x, h = blockIdx.y, m = threadIdx.x;
    float v = -1e30f;
    if (n < NT && m < NT) v = ab[h*NT + bidx[n*NT + m]];
    g_b[((size_t)h*NP + n)*NP + m] = v;
}

// ---------------- kernel 2/4: TF32 GEMM, 128x128, cp.async double-buffered ----
// operands are pre-converted tf32 bits -> zero cvt in the hot loop
template<bool QKV>
__global__ void __launch_bounds__(256) gemm_tf32(const uint32_t* __restrict__ W,
                                                 const float* __restrict__ bias,
                                                 float* __restrict__ C) {
    extern __shared__ uint32_t sm[];
    uint32_t* As = sm;                 // [2][128][36]
    uint32_t* Bs = sm + 2*128*36;      // [2][128][36]
    const uint32_t* A = QKV ? g_xn : g_att32;

    int tid  = threadIdx.x;
    int wid  = tid >> 5, lane = tid & 31;
    int warp_m = (wid >> 1) * 32;   // 0,32,64,96
    int warp_n = (wid & 1) * 64;    // 0,64
    int col0 = blockIdx.x * 128;
    int row0 = blockIdx.y * 128;

    int lr = tid >> 3;              // 0..31
    int lc = tid & 7;               // float4 slot in 32-wide k-tile
    uint32_t sA = (uint32_t)__cvta_generic_to_shared(As);
    uint32_t sB = (uint32_t)__cvta_generic_to_shared(Bs);

    float acc[2][8][4];
#pragma unroll
    for (int i = 0; i < 2; i++)
#pragma unroll
        for (int j = 0; j < 8; j++)
#pragma unroll
            for (int k = 0; k < 4; k++) acc[i][j][k] = 0.f;

    auto load_stage = [&](int st, int kt) {
#pragma unroll
        for (int it = 0; it < 4; it++) {
            int r = lr + it*32;
            cp_async16(sA + ((st*128 + r)*36 + lc*4)*4,
                       A + (size_t)(row0 + r)*DIM + kt + lc*4);
            cp_async16(sB + ((st*128 + r)*36 + lc*4)*4,
                       W + (size_t)(col0 + r)*DIM + kt + lc*4);
        }
    };

    const int T = DIM / 32;         // 12
    load_stage(0, 0);
    asm volatile("cp.async.commit_group;\n" ::);

    for (int t = 0; t < T; t++) {
        if (t + 1 < T) {
            load_stage((t+1)&1, (t+1)*32);
            asm volatile("cp.async.commit_group;\n" ::);
            asm volatile("cp.async.wait_group 1;\n" ::);
        } else {
            asm volatile("cp.async.wait_group 0;\n" ::);
        }
        __syncthreads();
        int st = t & 1;
        const uint32_t* Ab = As + st*128*36;
        const uint32_t* Bb = Bs + st*128*36;
#pragma unroll
        for (int ks = 0; ks < 4; ks++) {
            int kq = ks*8 + (lane & 3);
            uint32_t af[2][4], bf[8][2];
#pragma unroll
            for (int mt = 0; mt < 2; mt++) {
                int r = warp_m + mt*16 + (lane >> 2);
                af[mt][0] = Ab[(r   )*36 + kq];
                af[mt][1] = Ab[(r+8 )*36 + kq];
                af[mt][2] = Ab[(r   )*36 + kq+4];
                af[mt][3] = Ab[(r+8 )*36 + kq+4];
            }
#pragma unroll
            for (int nt = 0; nt < 8; nt++) {
                int c = warp_n + nt*8 + (lane >> 2);
                bf[nt][0] = Bb[c*36 + kq];
                bf[nt][1] = Bb[c*36 + kq+4];
            }
#pragma unroll
            for (int mt = 0; mt < 2; mt++)
#pragma unroll
                for (int nt = 0; nt < 8; nt++)
                    mma_tf32(acc[mt][nt], af[mt], bf[nt]);
        }
        __syncthreads();
    }

#pragma unroll
    for (int mt = 0; mt < 2; mt++) {
#pragma unroll
        for (int nt = 0; nt < 8; nt++) {
#pragma unroll
            for (int i = 0; i < 4; i++) {
                int m  = row0 + warp_m + mt*16 + (lane >> 2) + ((i >> 1) * 8);
                int nn = col0 + warp_n + nt*8 + (lane & 3)*2 + (i & 1);
                float val = acc[mt][nt][i] + bias[nn];
                if (QKV) {
                    int b_ = m / NT, n_ = m - b_*NT;
                    int h  = nn / 96, c = nn - h*96;
                    size_t base = ((size_t)(b_*HH + h)*NT + n_);
                    if      (c < KD)   g_q32[base*KD + c]        = f2tf32(val * QK_SCALE);
                    else if (c < 2*KD) g_k32[base*KD + (c-KD)]   = f2tf32(val);
                    else               g_v32[base*VD + (c-2*KD)] = f2tf32(val);
                } else {
                    C[(size_t)m*DIM + nn] = val;
                }
            }
        }
    }
}

// ---------------- kernel 3: flash tensor-core attention -----------------------
// 7 warps, each warp a 16-row Q tile (2 iters over 13 tiles). Online softmax
// over 2 column chunks of 104 -> S fits in 52 regs -> 2 blocks/SM.
#define VT_PITCH 212
__global__ void __launch_bounds__(224, 2) attn_mma() {
    extern __shared__ uint32_t smu[];
    uint32_t* Ksh = smu;                 // [208][36] tf32 bits
    uint32_t* Vt  = smu + NP*36;         // [32][212] tf32 bits, token-permuted

    int bh = blockIdx.x;
    int b_ = bh / HH;
    int h  = bh - b_*HH;
    int tid = threadIdx.x, w = tid >> 5, lane = tid & 31;

    for (int i = tid; i < NP*8; i += 224) {
        int m = i >> 3, c4 = i & 7;
        uint4 kv = {0u,0u,0u,0u};
        if (m < NT) kv = *(const uint4*)(g_k32 + ((size_t)bh*NT + m)*KD + c4*4);
        *(uint4*)&Ksh[m*36 + c4*4] = kv;

        int p = m;
        int tok = (p & ~7) + 2*(p & 3) + ((p >> 2) & 1);
        uint4 vv = {0u,0u,0u,0u};
        if (tok < NT) vv = *(const uint4*)(g_v32 + ((size_t)bh*NT + tok)*VD + c4*4);
        Vt[(c4*4+0)*VT_PITCH + p] = vv.x;
        Vt[(c4*4+1)*VT_PITCH + p] = vv.y;
        Vt[(c4*4+2)*VT_PITCH + p] = vv.z;
        Vt[(c4*4+3)*VT_PITCH + p] = vv.w;
    }
    __syncthreads();

    for (int iter = 0; iter < 2; iter++) {
        int tile = w + iter*7;
        if (tile >= 13) break;
        int r0 = tile*16 + (lane >> 2);
        int r1 = r0 + 8;

        // Q fragments (pre-scaled tf32 bits)
        uint32_t qa[4][4];
        const uint32_t* q0p = g_q32 + ((size_t)bh*NT + r0)*KD;
        const uint32_t* q1p = g_q32 + ((size_t)bh*NT + r1)*KD;
#pragma unroll
        for (int kt = 0; kt < 4; kt++) {
            int k0 = kt*8 + (lane & 3);
            qa[kt][0] = (r0 < NT) ? q0p[k0    ] : 0u;
            qa[kt][1] = (r1 < NT) ? q1p[k0    ] : 0u;
            qa[kt][2] = (r0 < NT) ? q0p[k0 + 4] : 0u;
            qa[kt][3] = (r1 < NT) ? q1p[k0 + 4] : 0u;
        }

        const float* gb0 = g_b + ((size_t)h*NP + r0)*NP;
        const float* gb1 = g_b + ((size_t)h*NP + r1)*NP;

        float m0 = -1e30f, m1 = -1e30f, l0 = 0.f, l1 = 0.f;
        float o[4][4];
#pragma unroll
        for (int vt = 0; vt < 4; vt++) { o[vt][0]=0.f; o[vt][1]=0.f; o[vt][2]=0.f; o[vt][3]=0.f; }

#pragma unroll
        for (int ch = 0; ch < 2; ch++) {
            int cb = ch * 104;
            float s[13][4];
#pragma unroll
            for (int nt = 0; nt < 13; nt++) { s[nt][0]=0.f; s[nt][1]=0.f; s[nt][2]=0.f; s[nt][3]=0.f; }
#pragma unroll
            for (int nt = 0; nt < 13; nt++) {
                int c = cb + nt*8 + (lane >> 2);
#pragma unroll
                for (int kt = 0; kt < 4; kt++) {
                    uint32_t bfr[2];
                    bfr[0] = Ksh[c*36 + kt*8 + (lane & 3)];
                    bfr[1] = Ksh[c*36 + kt*8 + (lane & 3) + 4];
                    mma_tf32(s[nt], qa[kt], bfr);
                }
            }
            // + bias
#pragma unroll
            for (int nt = 0; nt < 13; nt++) {
                int cc = cb + nt*8 + 2*(lane & 3);
                float2 b0 = *(const float2*)(gb0 + cc);
                float2 b1 = *(const float2*)(gb1 + cc);
                s[nt][0] += b0.x; s[nt][1] += b0.y;
                s[nt][2] += b1.x; s[nt][3] += b1.y;
            }
            // chunk max
            float cm0 = -1e30f, cm1 = -1e30f;
#pragma unroll
            for (int nt = 0; nt < 13; nt++) {
                cm0 = fmaxf(cm0, fmaxf(s[nt][0], s[nt][1]));
                cm1 = fmaxf(cm1, fmaxf(s[nt][2], s[nt][3]));
            }
            cm0 = fmaxf(cm0, __shfl_xor_sync(0xffffffffu, cm0, 1));
            cm0 = fmaxf(cm0, __shfl_xor_sync(0xffffffffu, cm0, 2));
            cm1 = fmaxf(cm1, __shfl_xor_sync(0xffffffffu, cm1, 1));
            cm1 = fmaxf(cm1, __shfl_xor_sync(0xffffffffu, cm1, 2));
            float mn0 = fmaxf(m0, cm0), mn1 = fmaxf(m1, cm1);
            float sc0 = __expf(m0 - mn0), sc1 = __expf(m1 - mn1);
            m0 = mn0; m1 = mn1;
            // exponentiate + chunk sum
            float cs0 = 0.f, cs1 = 0.f;
#pragma unroll
            for (int nt = 0; nt < 13; nt++) {
                s[nt][0] = __expf(s[nt][0] - m0); cs0 += s[nt][0];
                s[nt][1] = __expf(s[nt][1] - m0); cs0 += s[nt][1];
                s[nt][2] = __expf(s[nt][2] - m1); cs1 += s[nt][2];
                s[nt][3] = __expf(s[nt][3] - m1); cs1 += s[nt][3];
            }
            cs0 += __shfl_xor_sync(0xffffffffu, cs0, 1);
            cs0 += __shfl_xor_sync(0xffffffffu, cs0, 2);
            cs1 += __shfl_xor_sync(0xffffffffu, cs1, 1);
            cs1 += __shfl_xor_sync(0xffffffffu, cs1, 2);
            l0 = l0*sc0 + cs0;
            l1 = l1*sc1 + cs1;
            // rescale O
#pragma unroll
            for (int vt = 0; vt < 4; vt++) {
                o[vt][0] *= sc0; o[vt][1] *= sc0;
                o[vt][2] *= sc1; o[vt][3] *= sc1;
            }
            // O += P V (P C-frag -> A-frag via V token permutation)
#pragma unroll
            for (int kt = 0; kt < 13; kt++) {
                uint32_t pa[4];
                pa[0] = f2tf32(s[kt][0]);
                pa[1] = f2tf32(s[kt][2]);
                pa[2] = f2tf32(s[kt][1]);
                pa[3] = f2tf32(s[kt][3]);
#pragma unroll
                for (int vt = 0; vt < 4; vt++) {
                    uint32_t bfr[2];
                    int d = vt*8 + (lane >> 2);
                    bfr[0] = Vt[d*VT_PITCH + cb + kt*8 + (lane & 3)];
                    bfr[1] = Vt[d*VT_PITCH + cb + kt*8 + (lane & 3) + 4];
                    mma_tf32(o[vt], pa, bfr);
                }
            }
        }

        float inv0 = __fdividef(1.f, l0);
        float inv1 = __fdividef(1.f, l1);
        if (r0 < NT) {
            uint32_t* orow = g_att32 + ((size_t)(b_*NT + r0))*DIM + h*VD;
#pragma unroll
            for (int vt = 0; vt < 4; vt++) {
                orow[vt*8 + 2*(lane & 3)    ] = f2tf32(o[vt][0]*inv0);
                orow[vt*8 + 2*(lane & 3) + 1] = f2tf32(o[vt][1]*inv0);
            }
        }
        if (r1 < NT) {
            uint32_t* orow = g_att32 + ((size_t)(b_*NT + r1))*DIM + h*VD;
#pragma unroll
            for (int vt = 0; vt < 4; vt++) {
                orow[vt*8 + 2*(lane & 3)    ] = f2tf32(o[vt][2]*inv1);
                orow[vt*8 + 2*(lane & 3) + 1] = f2tf32(o[vt][3]*inv1);
            }
        }
    }
}

// ---------------- launch ------------------------------------------------------
extern "C" void kernel_launch(void* const* d_in, const int* in_sizes, int n_in,
                              void* d_out, int out_size) {
    const float* x      = (const float*)d_in[0];
    const float* norm_w = (const float*)d_in[1];
    const float* norm_b = (const float*)d_in[2];
    const float* qkv_w  = (const float*)d_in[3];
    const float* qkv_b  = (const float*)d_in[4];
    const float* attb   = (const float*)d_in[5];
    const float* proj_w = (const float*)d_in[6];
    const float* proj_b = (const float*)d_in[7];
    const int*   bidx   = (const int*)  d_in[8];
    float* out = (float*)d_out;

    uint32_t* qkvw32;  cudaGetSymbolAddress((void**)&qkvw32,  g_qkvw32);
    uint32_t* projw32; cudaGetSymbolAddress((void**)&projw32, g_projw32);

    const int gemm_smem = 2 * 2 * 128 * 36 * (int)sizeof(uint32_t);       // 73728
    const int attn_smem = (NP*36 + 32*VT_PITCH) * (int)sizeof(uint32_t);  // 57088
    cudaFuncSetAttribute(gemm_tf32<true >, cudaFuncAttributeMaxDynamicSharedMemorySize, gemm_smem);
    cudaFuncSetAttribute(gemm_tf32<false>, cudaFuncAttributeMaxDynamicSharedMemorySize, gemm_smem);
    cudaFuncSetAttribute(attn_mma,         cudaFuncAttributeMaxDynamicSharedMemorySize, attn_smem);

    cvt_tf32_kernel<<<(FF*DIM + 255)/256,  256>>>(qkv_w,  qkvw32,  FF*DIM);
    cvt_tf32_kernel<<<(DIM*DIM + 255)/256, 256>>>(proj_w, projw32, DIM*DIM);
    ln_kernel<<<MM/8, 256>>>(x, norm_w, norm_b);
    bias_expand<<<dim3(NP, HH), NP>>>(attb, bidx);
    gemm_tf32<true ><<<dim3(FF/128,  MM/128), 256, gemm_smem>>>(qkvw32, qkv_b, nullptr);
    attn_mma<<<BB*HH, 224, attn_smem>>>();
    gemm_tf32<false><<<dim3(DIM/128, MM/128), 256, gemm_smem>>>(projw32, proj_b, out);
}